// round 15
// baseline (speedup 1.0000x reference)
#include <cuda_runtime.h>
#include <cstdint>

// DepthDeformConv: modulated deformable conv 3x3, s=1, p=1, d=1.
// B=4, C=64, H=W=128, O=64, K=9, fp32. Output (4,64,128,128) fp32.
//
// K0 (k_prep): bid<512: input NCHW -> NHWC8 g_in8[b][g][pix][8];
//              bid>=512: weights -> g_wt[(cc*72 + k*8 + cl)*64 + o].
// K1 (ddc_main): one block per (b,y); 320 threads; 2 blocks/SM.
//   Warp-specialized pipeline over 8 chunks (8ch = 72 col rows),
//   double-buffered col (2 x 36.9KB):
//     producers (warps 0-1, 64 thr): dense NHWC8 gather (R14-proven) into
//       col[buf]; handshake FULL/EMPTY named barriers (count 320).
//     consumers (warps 2-9, 256 thr): R5's exact FMA structure:
//       warp = (og: 16 outputs, s: ck half of 36 rows), lane = 4 pix;
//       acc[8][4] ull; weights via uniform __ldg; per row: 1 col LDS.128 +
//       4 packs + 4 w LDG.128 + 8 packs + 32 fma2.
//   Then consumer-only 2-way ck reduction via smem, bias, STG.128.

#define HW 128
#define PLANE 16384
#define CIN 64
#define OOUT 64
#define CKTOT 576
#define NJOBS 1152
#define RPC 72
#define NCHUNK 8
#define NTHREADS 320
#define COLBUF_B 36864                  // one col buffer: 72*128*4

#define OFF_MI 73728                    // col double buf: [0, 73728)
#define OFF_MW (OFF_MI + 9216)          // 82944
#define SMEM_TOTAL (OFF_MW + 18432)     // 101376

typedef unsigned long long ull;

__device__ float g_in8[4 * 8 * PLANE * 8];   // 16 MB
__device__ float g_wt[CKTOT * OOUT];

__device__ __forceinline__ ull pack2(float lo, float hi) {
    ull d;
    asm("mov.b64 %0, {%1, %2};" : "=l"(d) : "f"(lo), "f"(hi));
    return d;
}
__device__ __forceinline__ float2 unpack2(ull v) {
    float2 r;
    asm("mov.b64 {%0, %1}, %2;" : "=f"(r.x), "=f"(r.y) : "l"(v));
    return r;
}
__device__ __forceinline__ ull fma2(ull a, ull b, ull c) {
    ull d;
    asm("fma.rn.f32x2 %0, %1, %2, %3;" : "=l"(d) : "l"(a), "l"(b), "l"(c));
    return d;
}
__device__ __forceinline__ ull add2(ull a, ull b) {
    ull d;
    asm("add.rn.f32x2 %0, %1, %2;" : "=l"(d) : "l"(a), "l"(b));
    return d;
}
#define BSYNC(id, cnt) asm volatile("bar.sync %0, %1;" :: "r"(id), "r"(cnt) : "memory")
#define BARRV(id, cnt) asm volatile("bar.arrive %0, %1;" :: "r"(id), "r"(cnt) : "memory")

// ---------------- K0: fused prep ----------------
__global__ __launch_bounds__(256) void k_prep(const float* __restrict__ in,
                                              const float* __restrict__ w) {
    const int bid = blockIdx.x;
    const int tid = threadIdx.x;
    if (bid < 512) {
        __shared__ float t[64][129];
        const int y = bid & 127, b = bid >> 7;
        const float* ib = in + (size_t)b * CIN * PLANE + y * HW;
        #pragma unroll 8
        for (int it = 0; it < 32; it++) {
            int i = tid + it * 256;
            int c = i >> 7, x = i & 127;
            t[c][x] = __ldg(ib + c * PLANE + x);
        }
        __syncthreads();
        #pragma unroll 8
        for (int it = 0; it < 32; it++) {
            int i = tid + it * 256;
            int cl = i & 7, x = (i >> 3) & 127, g = i >> 10;
            g_in8[(((size_t)(b * 8 + g)) * PLANE + y * HW + x) * 8 + cl] = t[g * 8 + cl][x];
        }
    } else {
        int idx = (bid - 512) * 256 + tid;
        if (idx < OOUT * CKTOT) {
            int o = idx / CKTOT, rem = idx - o * CKTOT;
            int c = rem / 9, k = rem - c * 9;
            int cc = c >> 3, cl = c & 7;
            g_wt[(cc * RPC + k * 8 + cl) * OOUT + o] = w[idx];
        }
    }
}

// ---------------- K1: main ----------------
extern __shared__ char smraw[];

__global__ __launch_bounds__(NTHREADS, 2)
void ddc_main(const float* __restrict__ offset,
              const float* __restrict__ mask,
              const float* __restrict__ bias,
              float* __restrict__ out)
{
    short4* meta_i = (short4*)(smraw + OFF_MI);
    float4* meta_w = (float4*)(smraw + OFF_MW);

    const int tid = threadIdx.x;
    const int bid = blockIdx.x;
    const int y = bid & 127;
    const int b = bid >> 7;

    // ---- META: 1152 jobs, all 320 threads, once ----
    for (int i = tid; i < NJOBS; i += NTHREADS) {
        int pix = i & 127;
        int k   = i >> 7;
        int ky  = k / 3;
        int kx  = k - ky * 3;

        int ob = ((b * 18 + 2 * k) * HW + y) * HW + pix;
        float oy = __ldg(offset + ob);
        float ox = __ldg(offset + ob + PLANE);
        float m  = __ldg(mask + ((b * 9 + k) * HW + y) * HW + pix);

        float py = (float)(y - 1 + ky) + oy;
        float px = (float)(pix - 1 + kx) + ox;
        float y0f = floorf(py), x0f = floorf(px);
        int y0 = (int)y0f, x0 = (int)x0f;
        float wy = py - y0f, wx = px - x0f;
        int y1 = y0 + 1, x1 = x0 + 1;

        float vy0 = (y0 >= 0 && y0 < HW) ? 1.f : 0.f;
        float vy1 = (y1 >= 0 && y1 < HW) ? 1.f : 0.f;
        float vx0 = (x0 >= 0 && x0 < HW) ? 1.f : 0.f;
        float vx1 = (x1 >= 0 && x1 < HW) ? 1.f : 0.f;
        int yc0 = min(max(y0, 0), HW - 1);
        int yc1 = min(max(y1, 0), HW - 1);
        int xc0 = min(max(x0, 0), HW - 1);
        int xc1 = min(max(x1, 0), HW - 1);

        float4 w;
        w.x = (1.f - wy) * (1.f - wx) * m * vy0 * vx0;
        w.y = (1.f - wy) * wx         * m * vy0 * vx1;
        w.z = wy         * (1.f - wx) * m * vy1 * vx0;
        w.w = wy         * wx         * m * vy1 * vx1;

        meta_i[i] = make_short4((short)(yc0 * HW + xc0), (short)(yc0 * HW + xc1),
                                (short)(yc1 * HW + xc0), (short)(yc1 * HW + xc1));
        meta_w[i] = w;
    }
    __syncthreads();

    if (tid < 64) {
        // ================= PRODUCERS (warps 0-1) =================
        const int grp = tid >> 2;          // 0..15
        const int p   = tid & 3;           // channel pair
        for (int cc = 0; cc < NCHUNK; cc++) {
            int buf = cc & 1;
            if (cc >= 2) BSYNC(3 + buf, NTHREADS);     // wait EMPTY
            float* cb = (float*)(smraw + buf * COLBUF_B);
            const float2* nb = (const float2*)g_in8 + ((size_t)(b * 8 + cc)) * PLANE * 4;
            #pragma unroll 4
            for (int j = grp; j < NJOBS; j += 16) {
                short4 mi = meta_i[j];
                float4 mw = meta_w[j];
                float2 t00 = __ldg(nb + ((int)mi.x << 2) + p);
                float2 t01 = __ldg(nb + ((int)mi.y << 2) + p);
                float2 t10 = __ldg(nb + ((int)mi.z << 2) + p);
                float2 t11 = __ldg(nb + ((int)mi.w << 2) + p);
                float vx_ = mw.x * t00.x + mw.y * t01.x + mw.z * t10.x + mw.w * t11.x;
                float vy_ = mw.x * t00.y + mw.y * t01.y + mw.z * t10.y + mw.w * t11.y;
                int r   = (j >> 7) * 8 + 2 * p;
                int psw = (j & 127) ^ (p << 3);
                cb[r * 128 + psw]       = vx_;
                cb[(r + 1) * 128 + psw] = vy_;
            }
            __threadfence_block();
            BARRV(1 + buf, NTHREADS);                  // signal FULL
        }
    } else {
        // ================= CONSUMERS (warps 2-9) =================
        const int ctid = tid - 64;
        const int cwid = ctid >> 5;        // 0..7
        const int lane = ctid & 31;        // 4-pixel group
        const int og   = cwid & 3;         // 16 outputs: o base = og*16
        const int s    = cwid >> 2;        // ck half: rows [s*36, s*36+36)

        ull acc[8][4];
        #pragma unroll
        for (int j = 0; j < 8; j++)
            #pragma unroll
            for (int q = 0; q < 4; q++) acc[j][q] = 0ULL;

        for (int cc = 0; cc < NCHUNK; cc++) {
            int buf = cc & 1;
            BSYNC(1 + buf, NTHREADS);                  // wait FULL
            const float* cbuf = (const float*)(smraw + buf * COLBUF_B);
            const float4* wbase = (const float4*)(g_wt + (size_t)cc * RPC * OOUT + og * 16);
            #pragma unroll 2
            for (int row = s * 36; row < s * 36 + 36; row++) {
                int idx = (lane * 4) ^ (((row & 7) >> 1) << 3);
                float4 cq = *(const float4*)(cbuf + row * 128 + idx);
                ull cp0 = pack2(cq.x, cq.x);
                ull cp1 = pack2(cq.y, cq.y);
                ull cp2 = pack2(cq.z, cq.z);
                ull cp3 = pack2(cq.w, cq.w);
                const float4* wr = wbase + row * 16;
                #pragma unroll
                for (int j2 = 0; j2 < 4; j2++) {
                    float4 wq = __ldg(wr + j2);        // uniform, cached
                    ull wp0 = pack2(wq.x, wq.y);
                    ull wp1 = pack2(wq.z, wq.w);
                    int j = j2 * 2;
                    acc[j][0] = fma2(wp0, cp0, acc[j][0]);
                    acc[j][1] = fma2(wp0, cp1, acc[j][1]);
                    acc[j][2] = fma2(wp0, cp2, acc[j][2]);
                    acc[j][3] = fma2(wp0, cp3, acc[j][3]);
                    acc[j+1][0] = fma2(wp1, cp0, acc[j+1][0]);
                    acc[j+1][1] = fma2(wp1, cp1, acc[j+1][1]);
                    acc[j+1][2] = fma2(wp1, cp2, acc[j+1][2]);
                    acc[j+1][3] = fma2(wp1, cp3, acc[j+1][3]);
                }
            }
            if (cc < 6) BARRV(3 + buf, NTHREADS);      // signal EMPTY
        }

        // ---- 2-way ck reduction (consumer-only barrier id 5) ----
        ull* pr = (ull*)smraw;             // 128 slots x 32 u64 = 32KB
        const int slot = og * 32 + lane;
        BSYNC(5, 256);
        if (s == 1) {
            ull* rowp = pr + slot * 32;
            #pragma unroll
            for (int j = 0; j < 8; j++) {
                rowp[4*j]   = acc[j][0];
                rowp[4*j+1] = acc[j][1];
                rowp[4*j+2] = acc[j][2];
                rowp[4*j+3] = acc[j][3];
            }
        }
        BSYNC(5, 256);
        if (s == 0) {
            const ull* rowp = pr + slot * 32;
            #pragma unroll
            for (int j = 0; j < 8; j++) {
                int o0 = og * 16 + 2 * j;
                float bv0 = __ldg(bias + o0);
                float bv1 = __ldg(bias + o0 + 1);
                float4 re, ro;
                float2 v;
                v = unpack2(add2(acc[j][0], rowp[4*j]));   re.x = v.x + bv0; ro.x = v.y + bv1;
                v = unpack2(add2(acc[j][1], rowp[4*j+1])); re.y = v.x + bv0; ro.y = v.y + bv1;
                v = unpack2(add2(acc[j][2], rowp[4*j+2])); re.z = v.x + bv0; ro.z = v.y + bv1;
                v = unpack2(add2(acc[j][3], rowp[4*j+3])); re.w = v.x + bv0; ro.w = v.y + bv1;
                size_t base = (size_t)(b * OOUT + o0) * PLANE + y * HW + lane * 4;
                *(float4*)(out + base)         = re;
                *(float4*)(out + base + PLANE) = ro;
            }
        }
    }
}

extern "C" void kernel_launch(void* const* d_in, const int* in_sizes, int n_in,
                              void* d_out, int out_size)
{
    const float* input  = (const float*)d_in[0];
    // d_in[1] = depth, unused by the reference computation
    const float* offset = (const float*)d_in[2];
    const float* mask   = (const float*)d_in[3];
    const float* weight = (const float*)d_in[4];
    const float* bias   = (const float*)d_in[5];
    float* out = (float*)d_out;

    cudaFuncSetAttribute(ddc_main,
                         cudaFuncAttributeMaxDynamicSharedMemorySize, SMEM_TOTAL);

    k_prep<<<512 + 144, 256>>>(input, weight);
    ddc_main<<<512, NTHREADS, SMEM_TOTAL>>>(offset, mask, bias, out);
}

// round 17
// speedup vs baseline: 1.9160x; 1.9160x over previous
#include <cuda_runtime.h>
#include <cstdint>

// DepthDeformConv: modulated deformable conv 3x3, s=1, p=1, d=1.
// B=4, C=64, H=W=128, O=64, K=9, fp32. Output (4,64,128,128) fp32.
//
// R5 structure (best verified: 180.6us) with HALVED pixel tiles to kill the
// wave-quantization tail (512 blocks @ 3.46/SM -> makespan 2.0 block-times;
// 1024 blocks @ 6.92/SM -> 3.5, ~1% tail).
//
// K1 (k_prep): weight transpose g_wt[ck*64 + o] (R5 verbatim).
// K2 (ddc_main): one block per (b, y, x-half): 1024 blocks x 256 thr,
//   2 blocks/SM (73.8KB smem). K=576 in 4 chunks of 144 (16c x 9k):
//   - stage weight chunk [144][64] -> wsm (coalesced, R5 verbatim)
//   - gather: jobs = (k, 64 pix); bilinear meta in regs (R5 verbatim math),
//     reused over 16 channels; col[144][64] in smem (256B pitch)
//   - FMA: warp = 16-o group x ck-half; lane = 2 adjacent pixels (LDS.64,
//     naturally conflict-free); weight LDS.128 broadcast; acc[8][2].
//   - 2-way ck reduction via smem, bias, STG.64 epilogue.

#define HW 128
#define PLANE 16384
#define CIN 64
#define OOUT 64
#define CKTOT 576
#define CHUNK 144           // 16 c * 9 k
#define NCHUNK 4
#define PIXB 64             // pixels per block
#define COL_PITCH 64        // floats (256B)
#define NTHREADS 256

#define OFF_W   36864                        // col: [0, 36864)
#define SMEM_TOTAL (36864 + CHUNK * 64 * 4)  // 36864 + 36864 = 73728

typedef unsigned long long ull;

__device__ float g_wt[CKTOT * OOUT];   // weight transposed: [ck][o]

__device__ __forceinline__ ull pack2(float lo, float hi) {
    ull d;
    asm("mov.b64 %0, {%1, %2};" : "=l"(d) : "f"(lo), "f"(hi));
    return d;
}
__device__ __forceinline__ float2 unpack2(ull v) {
    float2 r;
    asm("mov.b64 {%0, %1}, %2;" : "=f"(r.x), "=f"(r.y) : "l"(v));
    return r;
}
__device__ __forceinline__ ull fma2(ull a, ull b, ull c) {
    ull d;
    asm("fma.rn.f32x2 %0, %1, %2, %3;" : "=l"(d) : "l"(a), "l"(b), "l"(c));
    return d;
}
__device__ __forceinline__ ull add2(ull a, ull b) {
    ull d;
    asm("add.rn.f32x2 %0, %1, %2;" : "=l"(d) : "l"(a), "l"(b));
    return d;
}

// one-time weight transpose: g_wt[ck*64 + o] = weight[o*576 + ck]
__global__ __launch_bounds__(256) void k_prep(const float* __restrict__ w) {
    int idx = blockIdx.x * 256 + threadIdx.x;
    if (idx >= OOUT * CKTOT) return;
    int o = idx / CKTOT, ck = idx - o * CKTOT;
    g_wt[ck * OOUT + o] = w[idx];
}

extern __shared__ char smraw[];

__global__ __launch_bounds__(NTHREADS, 2)
void ddc_main(const float* __restrict__ input,
              const float* __restrict__ offset,
              const float* __restrict__ mask,
              const float* __restrict__ bias,
              float* __restrict__ out)
{
    float* col   = (float*)smraw;              // [144][64]
    float* wsm_t = (float*)(smraw + OFF_W);    // [144][64]

    const int tid = threadIdx.x;
    const int bid = blockIdx.x;
    const int xh = bid & 1;            // x half
    const int y  = (bid >> 1) & 127;
    const int b  = bid >> 8;
    const int x0 = xh * PIXB;
    const int wid  = tid >> 5;
    const int lane = tid & 31;         // lane = 2-pixel group
    const int og   = wid & 3;          // o-group: 16 outputs, base og*16
    const int ckh  = wid >> 2;         // ck half: [ckh*72, +72) per chunk

    const float* inb = input + (size_t)b * CIN * PLANE;

    // acc[j][q]: o-pair j (o = og*16+2j, +2j+1), pixel q (pix = lane*2+q)
    ull acc[8][2];
    #pragma unroll
    for (int j = 0; j < 8; j++) { acc[j][0] = 0ULL; acc[j][1] = 0ULL; }

    for (int cc = 0; cc < NCHUNK; cc++) {
        const int c0 = cc * 16;
        __syncthreads();    // previous FMA phase done reading col/wsm_t

        // ---- stage transposed weight chunk [144][64] (coalesced copy) ----
        {
            const float4* src = (const float4*)(g_wt + cc * CHUNK * OOUT);
            float4* dst = (float4*)wsm_t;
            #pragma unroll
            for (int i = 0; i < 9; i++)
                dst[tid + i * NTHREADS] = src[tid + i * NTHREADS];
        }

        // ---- gather: 576 (k,pix) jobs, each loops 16 channels ----
        for (int i = tid; i < 9 * PIXB; i += NTHREADS) {
            int pix = i & 63;
            int k   = i >> 6;                  // 0..8
            int ky  = k / 3;
            int kx  = k - ky * 3;
            int x   = x0 + pix;

            int ob = ((b * 18 + 2 * k) * HW + y) * HW + x;
            float oy = __ldg(offset + ob);
            float ox = __ldg(offset + ob + PLANE);
            float m  = __ldg(mask + ((b * 9 + k) * HW + y) * HW + x);

            float py = (float)(y - 1 + ky) + oy;
            float px = (float)(x - 1 + kx) + ox;
            float y0f = floorf(py), x0f = floorf(px);
            int y0 = (int)y0f, xp0 = (int)x0f;
            float wy = py - y0f, wx = px - x0f;
            int y1 = y0 + 1, xp1 = xp0 + 1;

            float vy0 = (y0 >= 0 && y0 < HW) ? 1.f : 0.f;
            float vy1 = (y1 >= 0 && y1 < HW) ? 1.f : 0.f;
            float vx0 = (xp0 >= 0 && xp0 < HW) ? 1.f : 0.f;
            float vx1 = (xp1 >= 0 && xp1 < HW) ? 1.f : 0.f;
            int yc0 = min(max(y0, 0), HW - 1);
            int yc1 = min(max(y1, 0), HW - 1);
            int xc0 = min(max(xp0, 0), HW - 1);
            int xc1 = min(max(xp1, 0), HW - 1);

            float w00 = (1.f - wy) * (1.f - wx) * m * vy0 * vx0;
            float w01 = (1.f - wy) * wx         * m * vy0 * vx1;
            float w10 = wy         * (1.f - wx) * m * vy1 * vx0;
            float w11 = wy         * wx         * m * vy1 * vx1;

            int i00 = yc0 * HW + xc0;
            int i01 = yc0 * HW + xc1;
            int i10 = yc1 * HW + xc0;
            int i11 = yc1 * HW + xc1;

            const float* p = inb + (size_t)c0 * PLANE;
            float* cdst = col + k * COL_PITCH + pix;
            #pragma unroll 4
            for (int cl = 0; cl < 16; cl++) {
                float v = w00 * __ldg(p + i00) + w01 * __ldg(p + i01)
                        + w10 * __ldg(p + i10) + w11 * __ldg(p + i11);
                cdst[cl * 9 * COL_PITCH] = v;   // row ck = cl*9 + k
                p += PLANE;
            }
        }
        __syncthreads();

        // ---- FMA: ck half [ckh*72, +72), 18 iters of 4 ck ----
        #pragma unroll 1
        for (int ck = ckh * 72; ck < ckh * 72 + 72; ck += 4) {
            #pragma unroll
            for (int u = 0; u < 4; u++) {
                float2 cq = *(const float2*)(col + (ck + u) * COL_PITCH + lane * 2);
                ull cp0 = pack2(cq.x, cq.x);
                ull cp1 = pack2(cq.y, cq.y);
                const float* wrow = wsm_t + (ck + u) * OOUT + og * 16;
                #pragma unroll
                for (int j2 = 0; j2 < 4; j2++) {
                    float4 wq = *(const float4*)(wrow + j2 * 4);  // broadcast
                    ull wp0 = pack2(wq.x, wq.y);   // o-pair (4j2, 4j2+1)
                    ull wp1 = pack2(wq.z, wq.w);   // o-pair (4j2+2, 4j2+3)
                    int j = j2 * 2;
                    acc[j][0]   = fma2(wp0, cp0, acc[j][0]);
                    acc[j][1]   = fma2(wp0, cp1, acc[j][1]);
                    acc[j+1][0] = fma2(wp1, cp0, acc[j+1][0]);
                    acc[j+1][1] = fma2(wp1, cp1, acc[j+1][1]);
                }
            }
        }
    }

    // ---- reduction across the 2 ck halves (reuse wsm area) ----
    ull* pr = (ull*)(smraw + OFF_W);   // 128 slots x 16 u64 = 16KB
    const int slot = og * 32 + lane;
    __syncthreads();
    if (ckh == 1) {
        ull* rowp = pr + slot * 16;
        #pragma unroll
        for (int j = 0; j < 8; j++) {
            rowp[2*j]   = acc[j][0];
            rowp[2*j+1] = acc[j][1];
        }
    }
    __syncthreads();
    if (ckh == 0) {
        const ull* rowp = pr + slot * 16;
        #pragma unroll
        for (int j = 0; j < 8; j++) {
            int o0 = og * 16 + 2 * j;
            float bv0 = __ldg(bias + o0);
            float bv1 = __ldg(bias + o0 + 1);
            float2 a0 = unpack2(add2(acc[j][0], rowp[2*j]));     // (o0,o0+1)@pix0
            float2 a1 = unpack2(add2(acc[j][1], rowp[2*j+1]));   // (o0,o0+1)@pix1
            size_t base = (size_t)(b * OOUT + o0) * PLANE + y * HW + x0 + lane * 2;
            *(float2*)(out + base)         = make_float2(a0.x + bv0, a1.x + bv0);
            *(float2*)(out + base + PLANE) = make_float2(a0.y + bv1, a1.y + bv1);
        }
    }
}

extern "C" void kernel_launch(void* const* d_in, const int* in_sizes, int n_in,
                              void* d_out, int out_size)
{
    const float* input  = (const float*)d_in[0];
    // d_in[1] = depth, unused by the reference computation
    const float* offset = (const float*)d_in[2];
    const float* mask   = (const float*)d_in[3];
    const float* weight = (const float*)d_in[4];
    const float* bias   = (const float*)d_in[5];
    float* out = (float*)d_out;

    cudaFuncSetAttribute(ddc_main,
                         cudaFuncAttributeMaxDynamicSharedMemorySize, SMEM_TOTAL);

    k_prep<<<(OOUT * CKTOT + 255) / 256, 256>>>(weight);
    // grid: b (4) * y (128) * x-half (2) = 1024 blocks
    ddc_main<<<1024, NTHREADS, SMEM_TOTAL>>>(input, offset, mask, bias, out);
}